// round 16
// baseline (speedup 1.0000x reference)
#include <cuda_runtime.h>
#include <cuda_bf16.h>
#include <cstdint>
#include <cstddef>

#define N_HEADS 8
#define HEAD_DIM 16
#define IN_DIM 128
#define TI 16          // i-rows per attn block
#define TIP 8          // i-rows per proj block
#define TJ 64          // j-extent per attn block (= n / SPLIT)
#define SPLIT 8        // j-splits
#define MAXROWS 4096

#define LOG2E 1.4426950408889634f
#define C6K (0.6f * LOG2E)
#define C4K (0.4f * LOG2E)

typedef unsigned long long ull;

// Scratch (device globals: no allocation allowed)
__device__ __align__(16) float g_gl[MAXROWS * IN_DIM];
__device__ __align__(16) float g_gr[MAXROWS * IN_DIM];
__device__ __align__(16) float g_crK[MAXROWS * N_HEADS];   // interleaved [row][head]
// split-KV partials (plain sums; magnitudes bounded -> no running max needed)
__device__ __align__(16) float g_pacc[SPLIT * MAXROWS * IN_DIM];
__device__ __align__(16) float g_pl[SPLIT * MAXROWS * N_HEADS];
__device__ __align__(16) unsigned g_mbits[MAXROWS * 16];   // packed mask bits
__device__ unsigned g_cnt[512];                            // per-rowtile counters (zero-init; self-reset)

__device__ __forceinline__ float ex2(float x) {
    float y;
    asm("ex2.approx.ftz.f32 %0, %1;" : "=f"(y) : "f"(x));
    return y;
}
__device__ __forceinline__ void cp16(void* s, const void* g) {
    unsigned sa = (unsigned)__cvta_generic_to_shared(s);
    asm volatile("cp.async.cg.shared.global [%0], [%1], 16;" :: "r"(sa), "l"(g));
}
// ---- packed f32x2 helpers (Blackwell FFMA2 path) ----
__device__ __forceinline__ ull pk2(float lo, float hi) {
    ull r; asm("mov.b64 %0, {%1, %2};" : "=l"(r) : "f"(lo), "f"(hi)); return r;
}
__device__ __forceinline__ void upk(ull v, float& lo, float& hi) {
    asm("mov.b64 {%0, %1}, %2;" : "=f"(lo), "=f"(hi) : "l"(v));
}
__device__ __forceinline__ ull add2(ull a, ull b) {
    ull r; asm("add.rn.f32x2 %0, %1, %2;" : "=l"(r) : "l"(a), "l"(b)); return r;
}
__device__ __forceinline__ ull fma2(ull a, ull b, ull c) {
    ull r; asm("fma.rn.f32x2 %0, %1, %2, %3;" : "=l"(r) : "l"(a), "l"(b), "l"(c)); return r;
}

// ---------------------------------------------------------------------------
// Projection, L/R split: blockIdx.y = 0 -> gl (+ mask packing),
//                        blockIdx.y = 1 -> gr (+ crK score constants).
// Each block stages ONE weight matrix in 16-k double-buffered cp.async
// slices (smem 20KB). grid = (bn/8, 2) = 512 blocks.
// thread: col = t&127 (h,d), rg = t>>7 (4 rows, 2 f32x2 accumulators).
// ---------------------------------------------------------------------------
__global__ void __launch_bounds__(256) gat_proj(
    const float* __restrict__ H, const float* __restrict__ Wl,
    const float* __restrict__ Wr, const float* __restrict__ Wak,
    const uint8_t* __restrict__ mask, int n)
{
    __shared__ __align__(16) float hsT[IN_DIM * TIP];     // [k][i]  4KB
    __shared__ __align__(16) float Ws[2][16 * 128];       // 8KB x2

    int t = threadIdx.x;
    int r0 = blockIdx.x * TIP;
    int lr = blockIdx.y;                   // 0 = L, 1 = R
    int col = t & 127, rg = t >> 7;

    const float* W = lr ? Wr : Wl;

    // load H (8 rows x 128) transposed into hsT
    #pragma unroll
    for (int q = 0; q < 4; q++) {
        int idx = t + q * 256;
        int r = idx >> 7, k = idx & 127;
        hsT[k * TIP + r] = H[(size_t)(r0 + r) * IN_DIM + k];
    }

    // L-block only: pack mask bits (one uint32 per (row, 32-j group))
    if (lr == 0) {
        int words = n >> 5;
        int rl = t >> 4, w = t & 15;
        if (t < 128 && w < words) {
            const uint4* mv = (const uint4*)(mask + (size_t)(r0 + rl) * n + w * 32);
            uint4 m0 = mv[0], m1 = mv[1];
            unsigned bits;
            bits  = __dp4a(m0.x, 0x08040201u, 0u);
            bits |= __dp4a(m0.y, 0x08040201u, 0u) << 4;
            bits |= __dp4a(m0.z, 0x08040201u, 0u) << 8;
            bits |= __dp4a(m0.w, 0x08040201u, 0u) << 12;
            bits |= __dp4a(m1.x, 0x08040201u, 0u) << 16;
            bits |= __dp4a(m1.y, 0x08040201u, 0u) << 20;
            bits |= __dp4a(m1.z, 0x08040201u, 0u) << 24;
            bits |= __dp4a(m1.w, 0x08040201u, 0u) << 28;
            g_mbits[(size_t)(r0 + rl) * 16 + w] = bits;
        }
    }

    auto stageW = [&](int st, int kt) {
        int k0 = kt * 16;
        #pragma unroll
        for (int q = 0; q < 2; q++) {
            int c = t + q * 256;            // float4 chunk 0..511
            int kk = c >> 5, col4 = c & 31;
            int hh = col4 >> 2, dd4 = col4 & 3;
            size_t g = (size_t)hh * 2048 + (size_t)(k0 + kk) * 16 + dd4 * 4;
            cp16(&Ws[st][c * 4], W + g);
        }
        asm volatile("cp.async.commit_group;");
    };

    ull acc[2] = {0ull, 0ull};

    stageW(0, 0);
    for (int kt = 0; kt < 8; kt++) {
        if (kt + 1 < 8) {
            stageW((kt + 1) & 1, kt + 1);
            asm volatile("cp.async.wait_group 1;");
        } else {
            asm volatile("cp.async.wait_group 0;");
        }
        __syncthreads();
        int st = kt & 1;
        #pragma unroll
        for (int kk = 0; kk < 16; kk++) {
            float wv = Ws[st][kk * 128 + col];
            ull w2 = pk2(wv, wv);
            ulonglong2 h2 =
                *(const ulonglong2*)&hsT[(kt * 16 + kk) * TIP + rg * 4];
            acc[0] = fma2(h2.x, w2, acc[0]);
            acc[1] = fma2(h2.y, w2, acc[1]);
        }
        __syncthreads();
    }

    float* gout = lr ? g_gr : g_gl;
    float as[4];
    upk(acc[0], as[0], as[1]); upk(acc[1], as[2], as[3]);

    if (lr == 0) {
        #pragma unroll
        for (int i = 0; i < 4; i++) {
            size_t row = (size_t)(r0 + rg * 4 + i);
            gout[row * IN_DIM + col] = as[i];
        }
    } else {
        float w = Wak[col];               // Wak[h*16+d]
        int h = col >> 4;
        #pragma unroll
        for (int i = 0; i < 4; i++) {
            size_t row = (size_t)(r0 + rg * 4 + i);
            gout[row * IN_DIM + col] = as[i];
            float sr = as[i] * w;
            #pragma unroll
            for (int mk = 8; mk >= 1; mk >>= 1) {
                sr += __shfl_xor_sync(0xffffffffu, sr, mk);
            }
            if ((t & 15) == 0) {
                g_crK[row * N_HEADS + h] = C6K * sr;
            }
        }
    }
}

// ---------------------------------------------------------------------------
// Split-KV partial + fused combine (R15 body; lb(128,4) = 128-reg budget
// for deeper cross-iteration software pipelining).
// Block = 16 i-rows x 64 j's, 128 threads: t = hh*16 + il; full d per thread.
// ---------------------------------------------------------------------------
__global__ void __launch_bounds__(128, 4) gat_attn(
    const float* __restrict__ Wak, float* __restrict__ out, int n)
{
    __shared__ __align__(16) float grs[TJ * IN_DIM];     // 32KB
    __shared__ __align__(16) float crs[TJ * N_HEADS];    // 2KB
    __shared__ int sdone;

    int t = threadIdx.x;
    int hh = t >> 4, il = t & 15;
    int r0 = blockIdx.x * TI;
    int split = blockIdx.y;
    int batch = r0 / n;
    int jbase = split * (n / SPLIT);
    size_t row = (size_t)r0 + il;
    int dof = hh * HEAD_DIM;

    // prefetch the whole j-tile (single shot)
    {
        size_t gb = ((size_t)batch * n + jbase) * IN_DIM;
        #pragma unroll
        for (int q = 0; q < 16; q++) {
            int e = t + q * 128;            // float4 index 0..2047
            cp16(&grs[e * 4], &g_gr[gb + (size_t)e * 4]);
        }
        cp16(&crs[t * 4], &g_crK[((size_t)batch * n + jbase) * N_HEADS + t * 4]);
        asm volatile("cp.async.commit_group;");
    }

    ull glv2[8];
    float wk[16];
    {
        const ulonglong2* gp = (const ulonglong2*)&g_gl[row * IN_DIM + dof];
        #pragma unroll
        for (int q = 0; q < 4; q++) {
            ulonglong2 a = gp[q];
            glv2[q * 2]     = a.x;
            glv2[q * 2 + 1] = a.y;
        }
        const float* wp = Wak + dof;
        #pragma unroll
        for (int q = 0; q < 16; q++) wk[q] = C4K * wp[q];
    }
    int w0 = jbase >> 5;
    ull mb = (ull)g_mbits[row * 16 + w0] | ((ull)g_mbits[row * 16 + w0 + 1] << 32);

    float l = 0.f;
    ull acc2[8] = {0ull, 0ull, 0ull, 0ull, 0ull, 0ull, 0ull, 0ull};

    const float NEGINF = __int_as_float(0xff800000);

    asm volatile("cp.async.wait_group 0;");
    __syncthreads();

    #pragma unroll 4
    for (int jj = 0; jj < TJ; jj++) {
        const ulonglong2* vp = (const ulonglong2*)&grs[jj * IN_DIM + dof];
        ulonglong2 va = vp[0], vb = vp[1], vc = vp[2], vd = vp[3];
        ull v2[8] = {va.x, va.y, vb.x, vb.y, vc.x, vc.y, vd.x, vd.y};

        // 4 independent FFMA chains; s0 seeded with crK_j (base cancels in softmax)
        float s0 = crs[jj * N_HEADS + hh];
        float s1 = 0.f, s2 = 0.f, s3 = 0.f;
        #pragma unroll
        for (int q = 0; q < 2; q++) {
            float t0, t1, t2, t3, t4, t5, t6, t7;
            upk(add2(glv2[q * 4],     v2[q * 4]),     t0, t1);
            upk(add2(glv2[q * 4 + 1], v2[q * 4 + 1]), t2, t3);
            upk(add2(glv2[q * 4 + 2], v2[q * 4 + 2]), t4, t5);
            upk(add2(glv2[q * 4 + 3], v2[q * 4 + 3]), t6, t7);
            s0 = fmaf(wk[q * 8],     fabsf(t0), s0);   // |x| folds into FFMA
            s1 = fmaf(wk[q * 8 + 1], fabsf(t1), s1);
            s2 = fmaf(wk[q * 8 + 2], fabsf(t2), s2);
            s3 = fmaf(wk[q * 8 + 3], fabsf(t3), s3);
            s0 = fmaf(wk[q * 8 + 4], fabsf(t4), s0);
            s1 = fmaf(wk[q * 8 + 5], fabsf(t5), s1);
            s2 = fmaf(wk[q * 8 + 6], fabsf(t6), s2);
            s3 = fmaf(wk[q * 8 + 7], fabsf(t7), s3);
        }
        float s = (s0 + s1) + (s2 + s3);
        s = ((mb >> jj) & 1ull) ? NEGINF : s;           // masked -> exp2 = 0
        float p = ex2(s);
        l += p;
        ull p2 = pk2(p, p);
        #pragma unroll
        for (int q = 0; q < 8; q++)
            acc2[q] = fma2(p2, v2[q], acc2[q]);
    }

    // store partials
    {
        float av[16];
        #pragma unroll
        for (int q = 0; q < 8; q++) upk(acc2[q], av[q * 2], av[q * 2 + 1]);
        size_t pbase = ((size_t)split * MAXROWS + row) * IN_DIM + dof;
        #pragma unroll
        for (int q = 0; q < 4; q++) {
            float4 o = {av[q * 4], av[q * 4 + 1], av[q * 4 + 2], av[q * 4 + 3]};
            ((float4*)&g_pacc[pbase])[q] = o;
        }
        g_pl[((size_t)split * MAXROWS + row) * N_HEADS + hh] = l;
    }

    // fused combine: last block for this rowtile sums splits, normalizes, writes out
    __threadfence();
    __syncthreads();
    if (t == 0) {
        unsigned o = atomicAdd(&g_cnt[blockIdx.x], 1);
        sdone = (o == SPLIT - 1);
    }
    __syncthreads();
    if (sdone) {
        __threadfence();
        int rl = t >> 3, head = t & 7;     // 16 rows x 8 heads
        size_t orow = (size_t)r0 + rl;
        float lsum = 0.f;
        float4 s4[4];
        #pragma unroll
        for (int q = 0; q < 4; q++) s4[q] = make_float4(0.f, 0.f, 0.f, 0.f);
        #pragma unroll
        for (int sp = 0; sp < SPLIT; sp++) {
            lsum += g_pl[((size_t)sp * MAXROWS + orow) * N_HEADS + head];
            size_t pb = ((size_t)sp * MAXROWS + orow) * IN_DIM + head * HEAD_DIM;
            #pragma unroll
            for (int q = 0; q < 4; q++) {
                float4 a = ((const float4*)&g_pacc[pb])[q];
                s4[q].x += a.x; s4[q].y += a.y; s4[q].z += a.z; s4[q].w += a.w;
            }
        }
        float inv = __fdividef(1.0f, lsum);
        #pragma unroll
        for (int q = 0; q < 4; q++) {
            float4 o;
            o.x = fmaxf(s4[q].x * inv, 0.f);
            o.y = fmaxf(s4[q].y * inv, 0.f);
            o.z = fmaxf(s4[q].z * inv, 0.f);
            o.w = fmaxf(s4[q].w * inv, 0.f);
            ((float4*)&out[orow * IN_DIM + head * HEAD_DIM])[q] = o;
        }
        if (t == 0) g_cnt[blockIdx.x] = 0;   // reset for next graph replay
    }
}

// ---------------------------------------------------------------------------
extern "C" void kernel_launch(void* const* d_in, const int* in_sizes, int n_in,
                              void* d_out, int out_size) {
    const float*   H    = (const float*)d_in[0];
    const uint8_t* mask = (const uint8_t*)d_in[1];
    const float*   Wl   = (const float*)d_in[2];
    const float*   Wr   = (const float*)d_in[3];
    const float*   Wak  = (const float*)d_in[4];
    float* out = (float*)d_out;

    int bn = in_sizes[0] / IN_DIM;          // b*n rows
    int n  = in_sizes[1] / bn;              // b*n*n / (b*n)

    dim3 pg(bn / TIP, 2);
    gat_proj<<<pg, 256>>>(H, Wl, Wr, Wak, mask, n);
    dim3 ag(bn / TI, SPLIT);
    gat_attn<<<ag, 128>>>(Wak, out, n);
}

// round 17
// speedup vs baseline: 1.0477x; 1.0477x over previous
#include <cuda_runtime.h>
#include <cuda_bf16.h>
#include <cstdint>
#include <cstddef>

#define N_HEADS 8
#define HEAD_DIM 16
#define IN_DIM 128
#define TI 16          // i-rows per attn block
#define TIP 8          // i-rows per proj block
#define TJ 64          // j-extent per attn block (= n / SPLIT)
#define SPLIT 8        // j-splits
#define MAXROWS 4096

#define LOG2E 1.4426950408889634f
#define C6K (0.6f * LOG2E)
#define C4K (0.4f * LOG2E)

typedef unsigned long long ull;

// Scratch (device globals: no allocation allowed)
__device__ __align__(16) float g_gl[MAXROWS * IN_DIM];
__device__ __align__(16) float g_gr[MAXROWS * IN_DIM];
__device__ __align__(16) float g_crK[MAXROWS * N_HEADS];   // interleaved [row][head]
// split-KV partials (plain sums; magnitudes bounded -> no running max needed)
__device__ __align__(16) float g_pacc[SPLIT * MAXROWS * IN_DIM];
__device__ __align__(16) float g_pl[SPLIT * MAXROWS * N_HEADS];
__device__ __align__(16) unsigned g_mbits[MAXROWS * 16];   // packed mask bits
__device__ unsigned g_cnt[512];                            // per-rowtile counters (zero-init; self-reset)

__device__ __forceinline__ float ex2(float x) {
    float y;
    asm("ex2.approx.ftz.f32 %0, %1;" : "=f"(y) : "f"(x));
    return y;
}
__device__ __forceinline__ void cp16(void* s, const void* g) {
    unsigned sa = (unsigned)__cvta_generic_to_shared(s);
    asm volatile("cp.async.cg.shared.global [%0], [%1], 16;" :: "r"(sa), "l"(g));
}
// ---- packed f32x2 helpers (Blackwell FFMA2 path) ----
__device__ __forceinline__ ull pk2(float lo, float hi) {
    ull r; asm("mov.b64 %0, {%1, %2};" : "=l"(r) : "f"(lo), "f"(hi)); return r;
}
__device__ __forceinline__ void upk(ull v, float& lo, float& hi) {
    asm("mov.b64 {%0, %1}, %2;" : "=f"(lo), "=f"(hi) : "l"(v));
}
__device__ __forceinline__ ull add2(ull a, ull b) {
    ull r; asm("add.rn.f32x2 %0, %1, %2;" : "=l"(r) : "l"(a), "l"(b)); return r;
}
__device__ __forceinline__ ull fma2(ull a, ull b, ull c) {
    ull r; asm("fma.rn.f32x2 %0, %1, %2, %3;" : "=l"(r) : "l"(a), "l"(b), "l"(c)); return r;
}

// ---------------------------------------------------------------------------
// Projection + score constants + mask bit-packing.  R15's measured-best
// config: TIP=8, grid = bn/8 = 256, both W matrices staged together in
// 16-k double-buffered cp.async slices.  clK not computed (cancels).
// ---------------------------------------------------------------------------
__global__ void __launch_bounds__(256) gat_proj(
    const float* __restrict__ H, const float* __restrict__ Wl,
    const float* __restrict__ Wr, const float* __restrict__ Wak,
    const uint8_t* __restrict__ mask, int n)
{
    __shared__ __align__(16) float hsT[IN_DIM * TIP];     // [k][i]  4KB
    __shared__ __align__(16) float Wls[2][16 * 128];      // 8KB x2
    __shared__ __align__(16) float Wrs[2][16 * 128];      // 8KB x2

    int t = threadIdx.x;
    int r0 = blockIdx.x * TIP;
    int col = t & 127, rg = t >> 7;

    #pragma unroll
    for (int q = 0; q < 4; q++) {
        int idx = t + q * 256;
        int r = idx >> 7, k = idx & 127;
        hsT[k * TIP + r] = H[(size_t)(r0 + r) * IN_DIM + k];
    }

    // pack mask bits for our 8 rows: one uint32 per (row, 32-j group)
    {
        int words = n >> 5;
        int rl = t >> 4, w = t & 15;
        if (t < 128 && w < words) {
            const uint4* mv = (const uint4*)(mask + (size_t)(r0 + rl) * n + w * 32);
            uint4 m0 = mv[0], m1 = mv[1];
            unsigned bits;
            bits  = __dp4a(m0.x, 0x08040201u, 0u);
            bits |= __dp4a(m0.y, 0x08040201u, 0u) << 4;
            bits |= __dp4a(m0.z, 0x08040201u, 0u) << 8;
            bits |= __dp4a(m0.w, 0x08040201u, 0u) << 12;
            bits |= __dp4a(m1.x, 0x08040201u, 0u) << 16;
            bits |= __dp4a(m1.y, 0x08040201u, 0u) << 20;
            bits |= __dp4a(m1.z, 0x08040201u, 0u) << 24;
            bits |= __dp4a(m1.w, 0x08040201u, 0u) << 28;
            g_mbits[(size_t)(r0 + rl) * 16 + w] = bits;
        }
    }

    auto stageW = [&](int st, int kt) {
        int k0 = kt * 16;
        #pragma unroll
        for (int q = 0; q < 2; q++) {
            int c = t + q * 256;            // float4 chunk 0..511
            int kk = c >> 5, col4 = c & 31;
            int hh = col4 >> 2, dd4 = col4 & 3;
            size_t g = (size_t)hh * 2048 + (size_t)(k0 + kk) * 16 + dd4 * 4;
            cp16(&Wls[st][c * 4], Wl + g);
            cp16(&Wrs[st][c * 4], Wr + g);
        }
        asm volatile("cp.async.commit_group;");
    };

    ull aL[2] = {0ull, 0ull};
    ull aR[2] = {0ull, 0ull};

    stageW(0, 0);
    for (int kt = 0; kt < 8; kt++) {
        if (kt + 1 < 8) {
            stageW((kt + 1) & 1, kt + 1);
            asm volatile("cp.async.wait_group 1;");
        } else {
            asm volatile("cp.async.wait_group 0;");
        }
        __syncthreads();
        int st = kt & 1;
        #pragma unroll
        for (int kk = 0; kk < 16; kk++) {
            float wl = Wls[st][kk * 128 + col];
            float wr = Wrs[st][kk * 128 + col];
            ull wl2 = pk2(wl, wl);
            ull wr2 = pk2(wr, wr);
            ulonglong2 h2 =
                *(const ulonglong2*)&hsT[(kt * 16 + kk) * TIP + rg * 4];
            aL[0] = fma2(h2.x, wl2, aL[0]);
            aL[1] = fma2(h2.y, wl2, aL[1]);
            aR[0] = fma2(h2.x, wr2, aR[0]);
            aR[1] = fma2(h2.y, wr2, aR[1]);
        }
        __syncthreads();
    }

    float w = Wak[col];               // Wak[h*16+d]
    int h = col >> 4;
    float aLs[4], aRs[4];
    upk(aL[0], aLs[0], aLs[1]); upk(aL[1], aLs[2], aLs[3]);
    upk(aR[0], aRs[0], aRs[1]); upk(aR[1], aRs[2], aRs[3]);
    #pragma unroll
    for (int i = 0; i < 4; i++) {
        size_t row = (size_t)(r0 + rg * 4 + i);
        g_gl[row * IN_DIM + col] = aLs[i];
        g_gr[row * IN_DIM + col] = aRs[i];
        float sr = aRs[i] * w;
        #pragma unroll
        for (int mk = 8; mk >= 1; mk >>= 1) {
            sr += __shfl_xor_sync(0xffffffffu, sr, mk);
        }
        if ((t & 15) == 0) {
            g_crK[row * N_HEADS + h] = C6K * sr;
        }
    }
}

// ---------------------------------------------------------------------------
// Split-KV partial + fused combine (flat full-d body; base term cancelled;
// lb(128,4) = 128-reg budget for deep cross-iteration software pipelining —
// measured 28.1us at occ 20.5%).
// Block = 16 i-rows x 64 j's, 128 threads: t = hh*16 + il; full d per thread.
// ---------------------------------------------------------------------------
__global__ void __launch_bounds__(128, 4) gat_attn(
    const float* __restrict__ Wak, float* __restrict__ out, int n)
{
    __shared__ __align__(16) float grs[TJ * IN_DIM];     // 32KB
    __shared__ __align__(16) float crs[TJ * N_HEADS];    // 2KB
    __shared__ int sdone;

    int t = threadIdx.x;
    int hh = t >> 4, il = t & 15;
    int r0 = blockIdx.x * TI;
    int split = blockIdx.y;
    int batch = r0 / n;
    int jbase = split * (n / SPLIT);
    size_t row = (size_t)r0 + il;
    int dof = hh * HEAD_DIM;

    // prefetch the whole j-tile (single shot)
    {
        size_t gb = ((size_t)batch * n + jbase) * IN_DIM;
        #pragma unroll
        for (int q = 0; q < 16; q++) {
            int e = t + q * 128;            // float4 index 0..2047
            cp16(&grs[e * 4], &g_gr[gb + (size_t)e * 4]);
        }
        cp16(&crs[t * 4], &g_crK[((size_t)batch * n + jbase) * N_HEADS + t * 4]);
        asm volatile("cp.async.commit_group;");
    }

    ull glv2[8];
    float wk[16];
    {
        const ulonglong2* gp = (const ulonglong2*)&g_gl[row * IN_DIM + dof];
        #pragma unroll
        for (int q = 0; q < 4; q++) {
            ulonglong2 a = gp[q];
            glv2[q * 2]     = a.x;
            glv2[q * 2 + 1] = a.y;
        }
        const float* wp = Wak + dof;
        #pragma unroll
        for (int q = 0; q < 16; q++) wk[q] = C4K * wp[q];
    }
    int w0 = jbase >> 5;
    ull mb = (ull)g_mbits[row * 16 + w0] | ((ull)g_mbits[row * 16 + w0 + 1] << 32);

    float l = 0.f;
    ull acc2[8] = {0ull, 0ull, 0ull, 0ull, 0ull, 0ull, 0ull, 0ull};

    const float NEGINF = __int_as_float(0xff800000);

    asm volatile("cp.async.wait_group 0;");
    __syncthreads();

    #pragma unroll 4
    for (int jj = 0; jj < TJ; jj++) {
        const ulonglong2* vp = (const ulonglong2*)&grs[jj * IN_DIM + dof];
        ulonglong2 va = vp[0], vb = vp[1], vc = vp[2], vd = vp[3];
        ull v2[8] = {va.x, va.y, vb.x, vb.y, vc.x, vc.y, vd.x, vd.y};

        // 4 independent FFMA chains; s0 seeded with crK_j (base cancels in softmax)
        float s0 = crs[jj * N_HEADS + hh];
        float s1 = 0.f, s2 = 0.f, s3 = 0.f;
        #pragma unroll
        for (int q = 0; q < 2; q++) {
            float t0, t1, t2, t3, t4, t5, t6, t7;
            upk(add2(glv2[q * 4],     v2[q * 4]),     t0, t1);
            upk(add2(glv2[q * 4 + 1], v2[q * 4 + 1]), t2, t3);
            upk(add2(glv2[q * 4 + 2], v2[q * 4 + 2]), t4, t5);
            upk(add2(glv2[q * 4 + 3], v2[q * 4 + 3]), t6, t7);
            s0 = fmaf(wk[q * 8],     fabsf(t0), s0);   // |x| folds into FFMA
            s1 = fmaf(wk[q * 8 + 1], fabsf(t1), s1);
            s2 = fmaf(wk[q * 8 + 2], fabsf(t2), s2);
            s3 = fmaf(wk[q * 8 + 3], fabsf(t3), s3);
            s0 = fmaf(wk[q * 8 + 4], fabsf(t4), s0);
            s1 = fmaf(wk[q * 8 + 5], fabsf(t5), s1);
            s2 = fmaf(wk[q * 8 + 6], fabsf(t6), s2);
            s3 = fmaf(wk[q * 8 + 7], fabsf(t7), s3);
        }
        float s = (s0 + s1) + (s2 + s3);
        s = ((mb >> jj) & 1ull) ? NEGINF : s;           // masked -> exp2 = 0
        float p = ex2(s);
        l += p;
        ull p2 = pk2(p, p);
        #pragma unroll
        for (int q = 0; q < 8; q++)
            acc2[q] = fma2(p2, v2[q], acc2[q]);
    }

    // store partials
    {
        float av[16];
        #pragma unroll
        for (int q = 0; q < 8; q++) upk(acc2[q], av[q * 2], av[q * 2 + 1]);
        size_t pbase = ((size_t)split * MAXROWS + row) * IN_DIM + dof;
        #pragma unroll
        for (int q = 0; q < 4; q++) {
            float4 o = {av[q * 4], av[q * 4 + 1], av[q * 4 + 2], av[q * 4 + 3]};
            ((float4*)&g_pacc[pbase])[q] = o;
        }
        g_pl[((size_t)split * MAXROWS + row) * N_HEADS + hh] = l;
    }

    // fused combine: last block for this rowtile sums splits, normalizes, writes out
    __threadfence();
    __syncthreads();
    if (t == 0) {
        unsigned o = atomicAdd(&g_cnt[blockIdx.x], 1);
        sdone = (o == SPLIT - 1);
    }
    __syncthreads();
    if (sdone) {
        __threadfence();
        int rl = t >> 3, head = t & 7;     // 16 rows x 8 heads
        size_t orow = (size_t)r0 + rl;
        float lsum = 0.f;
        float4 s4[4];
        #pragma unroll
        for (int q = 0; q < 4; q++) s4[q] = make_float4(0.f, 0.f, 0.f, 0.f);
        #pragma unroll
        for (int sp = 0; sp < SPLIT; sp++) {
            lsum += g_pl[((size_t)sp * MAXROWS + orow) * N_HEADS + head];
            size_t pb = ((size_t)sp * MAXROWS + orow) * IN_DIM + head * HEAD_DIM;
            #pragma unroll
            for (int q = 0; q < 4; q++) {
                float4 a = ((const float4*)&g_pacc[pb])[q];
                s4[q].x += a.x; s4[q].y += a.y; s4[q].z += a.z; s4[q].w += a.w;
            }
        }
        float inv = __fdividef(1.0f, lsum);
        #pragma unroll
        for (int q = 0; q < 4; q++) {
            float4 o;
            o.x = fmaxf(s4[q].x * inv, 0.f);
            o.y = fmaxf(s4[q].y * inv, 0.f);
            o.z = fmaxf(s4[q].z * inv, 0.f);
            o.w = fmaxf(s4[q].w * inv, 0.f);
            ((float4*)&out[orow * IN_DIM + head * HEAD_DIM])[q] = o;
        }
        if (t == 0) g_cnt[blockIdx.x] = 0;   // reset for next graph replay
    }
}

// ---------------------------------------------------------------------------
extern "C" void kernel_launch(void* const* d_in, const int* in_sizes, int n_in,
                              void* d_out, int out_size) {
    const float*   H    = (const float*)d_in[0];
    const uint8_t* mask = (const uint8_t*)d_in[1];
    const float*   Wl   = (const float*)d_in[2];
    const float*   Wr   = (const float*)d_in[3];
    const float*   Wak  = (const float*)d_in[4];
    float* out = (float*)d_out;

    int bn = in_sizes[0] / IN_DIM;          // b*n rows
    int n  = in_sizes[1] / bn;              // b*n*n / (b*n)

    gat_proj<<<bn / TIP, 256>>>(H, Wl, Wr, Wak, mask, n);
    dim3 ag(bn / TI, SPLIT);
    gat_attn<<<ag, 128>>>(Wak, out, n);
}